// round 12
// baseline (speedup 1.0000x reference)
#include <cuda_runtime.h>
#include <cuda_fp16.h>

typedef unsigned long long u64;
typedef unsigned int u32;

#define B_   256
#define T_   512
#define NIN  512
#define H_   256
#define G3H  768
#define NC   101
#define CL   4
#define NBG  16
#define WROWS 192
#define WBYTES (WROWS * 512)
#define ABUF  16384
#define SMEM_GRU (WBYTES + 2 * ABUF + 64)   // + mbarriers

// ---- scratch ---------------------------------------------------------------
__device__ float  g_xg[(size_t)B_ * T_ * G3H];
__device__ __half g_xh[(size_t)B_ * T_ * NIN];
__device__ __half g_wh[G3H * NIN];
__device__ float  g_hT[B_ * H_];

// ---- ptx helpers -----------------------------------------------------------
__device__ __forceinline__ void lds4(u32& r0, u32& r1, u32& r2, u32& r3, u32 a) {
    asm volatile("ldmatrix.sync.aligned.m8n8.x4.shared.b16 {%0,%1,%2,%3}, [%4];"
                 : "=r"(r0), "=r"(r1), "=r"(r2), "=r"(r3) : "r"(a));
}
__device__ __forceinline__ void lds2(u32& r0, u32& r1, u32 a) {
    asm volatile("ldmatrix.sync.aligned.m8n8.x2.shared.b16 {%0,%1}, [%2];"
                 : "=r"(r0), "=r"(r1) : "r"(a));
}
__device__ __forceinline__ void mma16816(float* c, const u32* a, const u32* b) {
    asm volatile("mma.sync.aligned.m16n8k16.row.col.f32.f16.f16.f32 "
                 "{%0,%1,%2,%3}, {%4,%5,%6,%7}, {%8,%9}, {%0,%1,%2,%3};"
                 : "+f"(c[0]), "+f"(c[1]), "+f"(c[2]), "+f"(c[3])
                 : "r"(a[0]), "r"(a[1]), "r"(a[2]), "r"(a[3]), "r"(b[0]), "r"(b[1]));
}
__device__ __forceinline__ u32 mapa_(u32 addr, u32 rank) {
    u32 r; asm("mapa.shared::cluster.u32 %0, %1, %2;" : "=r"(r) : "r"(addr), "r"(rank));
    return r;
}
__device__ __forceinline__ void stclu(u32 addr, u32 v) {
    asm volatile("st.shared::cluster.u32 [%0], %1;" :: "r"(addr), "r"(v) : "memory");
}
__device__ __forceinline__ void cluster_arrive() {
    asm volatile("barrier.cluster.arrive.aligned;" ::: "memory");
}
__device__ __forceinline__ void cluster_wait() {
    asm volatile("barrier.cluster.wait.aligned;" ::: "memory");
}
__device__ __forceinline__ u32 ctarank() {
    u32 r; asm("mov.u32 %0, %%cluster_ctarank;" : "=r"(r)); return r;
}
__device__ __forceinline__ int sw7(int chunk, int row) {
    return (chunk & 24) | ((chunk ^ (row & 7)) & 7);
}
__device__ __forceinline__ void mbinit(u32 addr, u32 cnt) {
    asm volatile("mbarrier.init.shared.b64 [%0], %1;" :: "r"(addr), "r"(cnt) : "memory");
}
__device__ __forceinline__ void mbarr(u32 addr) {   // remote release arrive
    asm volatile("mbarrier.arrive.release.cluster.shared::cluster.b64 _, [%0];"
                 :: "r"(addr) : "memory");
}
__device__ __forceinline__ void mbwait(u32 addr, u32 parity) {
    u32 done;
    asm volatile(
        "{\n\t.reg .pred P;\n\t"
        "mbarrier.try_wait.parity.acquire.cluster.shared::cta.b64 P, [%1], %2;\n\t"
        "selp.b32 %0, 1, 0, P;\n\t}"
        : "=r"(done) : "r"(addr), "r"(parity) : "memory");
    if (!done) {
        asm volatile(
            "{\n\t.reg .pred P;\n"
            "W%=:\n\t"
            "mbarrier.try_wait.parity.acquire.cluster.shared::cta.b64 P, [%0], %1, 0x989680;\n\t"
            "@P bra D%=;\n\t"
            "bra W%=;\n"
            "D%=:\n\t}"
            :: "r"(addr), "r"(parity) : "memory");
    }
}
__device__ __forceinline__ float tanh_ap(float x) {
    float y; asm("tanh.approx.f32 %0, %1;" : "=f"(y) : "f"(x)); return y;
}
__device__ __forceinline__ void cpa(u32 dst, const void* src) {
    asm volatile("cp.async.cg.shared.global [%0], [%1], 16;" :: "r"(dst), "l"(src) : "memory");
}
__device__ __forceinline__ void cpcommit() {
    asm volatile("cp.async.commit_group;" ::: "memory");
}
template<int N> __device__ __forceinline__ void cpwait() {
    asm volatile("cp.async.wait_group %0;" :: "n"(N) : "memory");
}

// ---- fp32 -> fp16 convert --------------------------------------------------
__global__ void cvt2h(const float* __restrict__ in, __half2* __restrict__ out, int n2) {
    for (int i = blockIdx.x * blockDim.x + threadIdx.x; i < n2; i += gridDim.x * blockDim.x) {
        float2 v = ((const float2*)in)[i];
        out[i] = __floats2half2_rn(v.x, v.y);
    }
}

// ===========================================================================
// Kernel A: fp16 HMMA GEMM with 3-stage cp.async pipeline.
// xg = x @ W_ih^T + b_ih.  CTA tile 128x64, K-tile 32, 8 warps (4m x 2n).
// ===========================================================================
__global__ __launch_bounds__(256)
void hgemm(const __half* __restrict__ Ah, const __half* __restrict__ Wh,
           const float* __restrict__ bih) {
    __shared__ __align__(16) char hsm[3 * 8192 + 3 * 4096];
    const int tid = threadIdx.x;
    const int lane = tid & 31, warp = tid >> 5;
    const int wm = warp & 3, wn = warp >> 2;
    const size_t mBase = (size_t)blockIdx.y * 128;
    const int nBase = blockIdx.x * 64;

    const int lr = tid >> 2, lc = tid & 3;
    const uint4* aG0 = (const uint4*)(Ah + (mBase + lr) * NIN) + lc;
    const uint4* aG1 = aG0 + (64 * NIN) / 8;
    const uint4* bG  = (const uint4*)(Wh + (size_t)(nBase + lr) * NIN) + lc;
    const int stA = lr * 64 + ((lc ^ ((lr >> 1) & 3)) * 16);

    const u32 aSm = (u32)__cvta_generic_to_shared(hsm);
    const u32 bSm = aSm + 3 * 8192;

    const int rowA = wm * 32 + ((lane >> 3) & 1) * 8 + (lane & 7);
    const int loffA = rowA * 64 + (((lane >> 4) ^ ((rowA >> 1) & 3)) * 16);
    const int rowB = wn * 32 + (lane >> 4) * 8 + (lane & 7);
    const int loffB = rowB * 64 + ((((lane >> 3) & 1) ^ ((rowB >> 1) & 3)) * 16);

    float c[2][4][4];
    #pragma unroll
    for (int mi = 0; mi < 2; mi++)
        #pragma unroll
        for (int ni = 0; ni < 4; ni++)
            #pragma unroll
            for (int q = 0; q < 4; q++) c[mi][ni][q] = 0.f;

    // prologue: stages 0,1
    #pragma unroll
    for (int p = 0; p < 2; p++) {
        const u32 da = aSm + p * 8192 + stA;
        cpa(da,        aG0 + p * 4);
        cpa(da + 4096, aG1 + p * 4);
        cpa(bSm + p * 4096 + stA, bG + p * 4);
        cpcommit();
    }

    int slotc = 0, slotl = 2;
    for (int kt = 0; kt < 16; kt++) {
        cpwait<1>();
        __syncthreads();
        if (kt + 2 < 16) {
            const u32 da = aSm + slotl * 8192 + stA;
            cpa(da,        aG0 + (kt + 2) * 4);
            cpa(da + 4096, aG1 + (kt + 2) * 4);
            cpa(bSm + slotl * 4096 + stA, bG + (kt + 2) * 4);
        }
        cpcommit();
        const u32 aB = aSm + slotc * 8192;
        const u32 bB = bSm + slotc * 4096;
        #pragma unroll
        for (int t = 0; t < 2; t++) {
            u32 aF[2][4], bF4[2][4];
            lds4(aF[0][0], aF[0][1], aF[0][2], aF[0][3], aB + (loffA ^ (t << 5)));
            lds4(aF[1][0], aF[1][1], aF[1][2], aF[1][3], aB + ((loffA + 1024) ^ (t << 5)));
            lds4(bF4[0][0], bF4[0][1], bF4[0][2], bF4[0][3], bB + (loffB ^ (t << 5)));
            lds4(bF4[1][0], bF4[1][1], bF4[1][2], bF4[1][3], bB + ((loffB + 1024) ^ (t << 5)));
            #pragma unroll
            for (int mi = 0; mi < 2; mi++) {
                mma16816(c[mi][0], aF[mi], &bF4[0][0]);
                mma16816(c[mi][1], aF[mi], &bF4[0][2]);
                mma16816(c[mi][2], aF[mi], &bF4[1][0]);
                mma16816(c[mi][3], aF[mi], &bF4[1][2]);
            }
        }
        slotc = (slotc + 1 == 3) ? 0 : slotc + 1;
        slotl = (slotl + 1 == 3) ? 0 : slotl + 1;
    }

    const int er = lane >> 2, ec = (lane & 3) * 2;
    #pragma unroll
    for (int mi = 0; mi < 2; mi++) {
        const size_t m0 = mBase + wm * 32 + mi * 16 + er;
        #pragma unroll
        for (int ni = 0; ni < 4; ni++) {
            const int col = nBase + wn * 32 + ni * 8 + ec;
            const float2 bv = *(const float2*)&bih[col];
            float2 o0 = make_float2(c[mi][ni][0] + bv.x, c[mi][ni][1] + bv.y);
            float2 o1 = make_float2(c[mi][ni][2] + bv.x, c[mi][ni][3] + bv.y);
            *(float2*)(g_xg + m0 * G3H + col)       = o0;
            *(float2*)(g_xg + (m0 + 8) * G3H + col) = o1;
        }
    }
}

// ===========================================================================
// Kernel B: tensor-core GRU, W fragments in registers, mbarrier pipeline.
// full[X]/empty[X] mbarriers (count 32 = all cluster warps). Per step:
//   wait full[cur] -> ldmatrix/MMA -> arrive empty[cur] -> gates ->
//   wait empty[nxt] -> DSMEM stores -> arrive full[nxt] -> xg prefetch.
// Both waits at step s use parity ((s-1)>>1)&1; s=0 waits are skipped.
// ===========================================================================
__global__ __launch_bounds__(256, 1) __cluster_dims__(CL, 1, 1)
void gru_mma(const float* __restrict__ Whh, const float* __restrict__ bhh) {
    extern __shared__ char sm[];
    char* WS = sm;                 // W staging (dead after prologue)
    char* AS = sm + WBYTES;        // [2 bufs][hi 8KB | lo 8KB]

    const int tid = threadIdx.x;
    const int lane = tid & 31, warp = tid >> 5;
    const u32 q = ctarank();
    const int b0 = (blockIdx.x >> 2) * NBG;

    const u32 asS = (u32)__cvta_generic_to_shared(AS);
    const u32 mbL = asS + 2 * ABUF;          // full0, full1, empty0, empty1 (8B each)

    if (tid == 0) {
        mbinit(mbL,      32); mbinit(mbL + 8,  32);
        mbinit(mbL + 16, 32); mbinit(mbL + 24, 32);
    }

    // ---- prologue: stage + convert + swizzle W slice ----
    for (int t = tid; t < WROWS * 32; t += 256) {
        int row = t >> 5, ch = t & 31;
        int jt = row / 24, rem = row - jt * 24;
        int g = rem >> 3, rr = rem & 7;
        int grow = g * 256 + (int)q * 64 + jt * 8 + rr;
        const float4* src = (const float4*)(Whh + (size_t)grow * H_ + ch * 8);
        float4 f0 = src[0], f1 = src[1];
        __half2 h0 = __floats2half2_rn(f0.x, f0.y), h1 = __floats2half2_rn(f0.z, f0.w);
        __half2 h2 = __floats2half2_rn(f1.x, f1.y), h3 = __floats2half2_rn(f1.z, f1.w);
        uint4 v = make_uint4(*(u32*)&h0, *(u32*)&h1, *(u32*)&h2, *(u32*)&h3);
        *(uint4*)(WS + row * 512 + sw7(ch, row) * 16) = v;
    }
    for (int t = tid; t < (2 * ABUF) / 16; t += 256)
        ((uint4*)AS)[t] = make_uint4(0, 0, 0, 0);
    __syncthreads();

    // ---- hoist W fragments to registers ----
    const u32 wsS = (u32)__cvta_generic_to_shared(WS);
    const int brow = warp * 24 + ((lane >> 4) & 1) * 8 + (lane & 7);
    const int bchl = (lane >> 3) & 1;
    const int nrow = warp * 24 + 16 + (lane & 7);
    u32 bR[16][2], bZ[16][2], bN[16][2];
    #pragma unroll
    for (int kc = 0; kc < 16; kc++) {
        const int cB = kc * 2 + bchl;
        u32 t0, t1, t2, t3;
        lds4(t0, t1, t2, t3, wsS + brow * 512 + sw7(cB, brow) * 16);
        bR[kc][0] = t0; bR[kc][1] = t1; bZ[kc][0] = t2; bZ[kc][1] = t3;
        lds2(bN[kc][0], bN[kc][1], wsS + nrow * 512 + sw7(cB, nrow) * 16);
    }

    // ---- per-thread constants ----
    const int jl = (lane & 3) * 2;
    const int jg = (int)q * 64 + warp * 8 + jl;
    const int m_ = lane >> 2;
    const float2 br = *(const float2*)&bhh[jg];
    const float2 bz = *(const float2*)&bhh[256 + jg];
    const float2 bq = *(const float2*)&bhh[512 + jg];

    const float* xg0 = g_xg + (size_t)(b0 + m_) * T_ * G3H + jg;
    const float* xg1 = g_xg + (size_t)(b0 + m_ + 8) * T_ * G3H + jg;

    const int arow = ((lane >> 3) & 1) * 8 + (lane & 7);
    const int achl = (lane >> 4) & 1;
    const int chw = (int)q * 8 + warp;
    const u32 woff0 = m_ * 512 + sw7(chw, m_) * 16 + (lane & 3) * 4;
    const u32 woff1 = woff0 + 8 * 512;

    u32 asR[CL], mbR[CL];
    #pragma unroll
    for (int r = 0; r < CL; r++) {
        asR[r] = mapa_(asS, (u32)r);
        mbR[r] = mapa_(mbL, (u32)r);
    }

    float hOld[4] = {0.f, 0.f, 0.f, 0.f};
    float2 xr0 = *(const float2*)xg0;
    float2 xz0 = *(const float2*)(xg0 + 256);
    float2 xn0 = *(const float2*)(xg0 + 512);
    float2 xr1 = *(const float2*)xg1;
    float2 xz1 = *(const float2*)(xg1 + 256);
    float2 xn1 = *(const float2*)(xg1 + 512);

    cluster_arrive(); cluster_wait();   // mbar init + zeroed buf0 visible

    for (int s = 0; s < T_; s++) {
        const u32 cu8 = (u32)(s & 1) * 8;
        const u32 nx8 = (u32)((s + 1) & 1) * 8;
        const u32 p = (u32)(((s - 1) >> 1) & 1);

        if (s > 0) mbwait(mbL + cu8, p);

        const u32 abase = asS + (u32)(s & 1) * ABUF;
        float crh[4] = {0,0,0,0}, czh[4] = {0,0,0,0}, cnh[4] = {0,0,0,0};
        float crl[4] = {0,0,0,0}, czl[4] = {0,0,0,0}, cnl[4] = {0,0,0,0};
        #pragma unroll
        for (int kc = 0; kc < 16; kc++) {
            const int cA = kc * 2 + achl;
            const u32 aaddr = abase + arow * 512 + sw7(cA, arow) * 16;
            u32 ah[4], al[4];
            lds4(ah[0], ah[1], ah[2], ah[3], aaddr);
            lds4(al[0], al[1], al[2], al[3], aaddr + 8192);
            mma16816(crh, ah, bR[kc]);
            mma16816(czh, ah, bZ[kc]);
            mma16816(cnh, ah, bN[kc]);
            mma16816(crl, al, bR[kc]);
            mma16816(czl, al, bZ[kc]);
            mma16816(cnl, al, bN[kc]);
        }
        __syncwarp();
        if (lane == 0) {   // reads done: release buffer cur to producers
            #pragma unroll
            for (int r = 0; r < CL; r++) mbarr(mbR[r] + 16 + cu8);
        }

        // ---- gates ----
        float hv[4];
        {
            const float xr[4] = {xr0.x, xr0.y, xr1.x, xr1.y};
            const float xz[4] = {xz0.x, xz0.y, xz1.x, xz1.y};
            const float xn[4] = {xn0.x, xn0.y, xn1.x, xn1.y};
            const float brv[4] = {br.x, br.y, br.x, br.y};
            const float bzv[4] = {bz.x, bz.y, bz.x, bz.y};
            const float bnv[4] = {bq.x, bq.y, bq.x, bq.y};
            #pragma unroll
            for (int i = 0; i < 4; i++) {
                float rr = __fdividef(1.f, 1.f + __expf(-(xr[i] + crh[i] + crl[i] + brv[i])));
                float zz = __fdividef(1.f, 1.f + __expf(-(xz[i] + czh[i] + czl[i] + bzv[i])));
                float nn = tanh_ap(xn[i] + rr * (cnh[i] + cnl[i] + bnv[i]));
                hv[i] = (1.f - zz) * nn + zz * hOld[i];
                hOld[i] = hv[i];
            }
        }

        if (s < T_ - 1) {
            if (s > 0) mbwait(mbL + 16 + nx8, p);
            __half2 hi0 = __floats2half2_rn(hv[0], hv[1]);
            __half2 hi1 = __floats2half2_rn(hv[2], hv[3]);
            float2 f0 = __half22float2(hi0), f1 = __half22float2(hi1);
            __half2 lo0 = __floats2half2_rn(hv[0] - f0.x, hv[1] - f0.y);
            __half2 lo1 = __floats2half2_rn(hv[2] - f1.x, hv[3] - f1.y);
            const u32 nbuf = (u32)((s + 1) & 1) * ABUF;
            #pragma unroll
            for (int r = 0; r < CL; r++) {
                const u32 base = asR[r] + nbuf;
                stclu(base + woff0,        *(u32*)&hi0);
                stclu(base + woff0 + 8192, *(u32*)&lo0);
                stclu(base + woff1,        *(u32*)&hi1);
                stclu(base + woff1 + 8192, *(u32*)&lo1);
            }
            __syncwarp();
            if (lane == 0) {
                #pragma unroll
                for (int r = 0; r < CL; r++) mbarr(mbR[r] + nx8);
            }
            // prefetch next xg under peers' latency
            const float* p0 = xg0 + (size_t)(s + 1) * G3H;
            const float* p1 = xg1 + (size_t)(s + 1) * G3H;
            xr0 = *(const float2*)p0;
            xz0 = *(const float2*)(p0 + 256);
            xn0 = *(const float2*)(p0 + 512);
            xr1 = *(const float2*)p1;
            xz1 = *(const float2*)(p1 + 256);
            xn1 = *(const float2*)(p1 + 512);
        } else {
            *(float2*)(g_hT + (size_t)(b0 + m_) * H_ + jg)     = make_float2(hv[0], hv[1]);
            *(float2*)(g_hT + (size_t)(b0 + m_ + 8) * H_ + jg) = make_float2(hv[2], hv[3]);
        }
    }
    cluster_arrive(); cluster_wait();   // no early exit while remote ops in flight
}

// ===========================================================================
// Kernel C: out[b,c] = hT[b] . fc_w[c] + fc_b[c]
// ===========================================================================
#define NBF 8
__global__ void fc_kernel(const float* __restrict__ fcw,
                          const float* __restrict__ fcb,
                          float* __restrict__ out) {
    __shared__ float hs[NBF][H_];
    const int b0 = blockIdx.x * NBF;
    for (int i = threadIdx.x; i < NBF * H_; i += blockDim.x)
        hs[i >> 8][i & 255] = g_hT[(size_t)b0 * H_ + i];
    __syncthreads();
    const int c = threadIdx.x;
    if (c < NC) {
        float acc[NBF];
        #pragma unroll
        for (int b = 0; b < NBF; b++) acc[b] = fcb[c];
        const float* w = fcw + (size_t)c * H_;
        #pragma unroll 4
        for (int k = 0; k < H_; k++) {
            float wv = w[k];
            #pragma unroll
            for (int b = 0; b < NBF; b++) acc[b] = fmaf(hs[b][k], wv, acc[b]);
        }
        #pragma unroll
        for (int b = 0; b < NBF; b++) out[(size_t)(b0 + b) * NC + c] = acc[b];
    }
}

// ===========================================================================
extern "C" void kernel_launch(void* const* d_in, const int* in_sizes, int n_in,
                              void* d_out, int out_size) {
    const float* x   = (const float*)d_in[0];
    const float* Wih = (const float*)d_in[1];
    const float* Whh = (const float*)d_in[2];
    const float* bih = (const float*)d_in[3];
    const float* bhh = (const float*)d_in[4];
    const float* fcw = (const float*)d_in[5];
    const float* fcb = (const float*)d_in[6];
    float* out = (float*)d_out;

    cudaFuncSetAttribute(gru_mma,
                         cudaFuncAttributeMaxDynamicSharedMemorySize, SMEM_GRU);

    __half2* xh2; cudaGetSymbolAddress((void**)&xh2, g_xh);
    __half2* wh2; cudaGetSymbolAddress((void**)&wh2, g_wh);

    cvt2h<<<2048, 256>>>(x, xh2, (B_ * T_ * NIN) / 2);
    cvt2h<<<256, 256>>>(Wih, wh2, (G3H * NIN) / 2);

    __half* xh; cudaGetSymbolAddress((void**)&xh, g_xh);
    __half* wh; cudaGetSymbolAddress((void**)&wh, g_wh);
    dim3 g1(G3H / 64, (B_ * T_) / 128);
    hgemm<<<g1, 256>>>(xh, wh, bih);

    gru_mma<<<16 * CL, 256, SMEM_GRU>>>(Whh, bhh);
    fc_kernel<<<B_ / NBF, 128>>>(fcw, fcb, out);
}

// round 14
// speedup vs baseline: 1.7575x; 1.7575x over previous
#include <cuda_runtime.h>
#include <cuda_fp16.h>

typedef unsigned long long u64;
typedef unsigned int u32;

#define B_   256
#define T_   512
#define NIN  512
#define H_   256
#define G3H  768
#define NC   101
#define CL   4
#define NBG  16
#define WROWS 192
#define WBYTES (WROWS * 512)
#define ABUF  16384
#define SMEM_GRU (WBYTES + 2 * ABUF)   // 131072

// ---- scratch ---------------------------------------------------------------
__device__ float  g_xg[(size_t)B_ * T_ * G3H];
__device__ __half g_xh[(size_t)B_ * T_ * NIN];
__device__ __half g_wh[G3H * NIN];
__device__ float  g_hT[B_ * H_];

// ---- ptx helpers -----------------------------------------------------------
__device__ __forceinline__ void lds4(u32& r0, u32& r1, u32& r2, u32& r3, u32 a) {
    asm volatile("ldmatrix.sync.aligned.m8n8.x4.shared.b16 {%0,%1,%2,%3}, [%4];"
                 : "=r"(r0), "=r"(r1), "=r"(r2), "=r"(r3) : "r"(a));
}
__device__ __forceinline__ void lds2(u32& r0, u32& r1, u32 a) {
    asm volatile("ldmatrix.sync.aligned.m8n8.x2.shared.b16 {%0,%1}, [%2];"
                 : "=r"(r0), "=r"(r1) : "r"(a));
}
__device__ __forceinline__ void mma16816(float* c, const u32* a, const u32* b) {
    asm volatile("mma.sync.aligned.m16n8k16.row.col.f32.f16.f16.f32 "
                 "{%0,%1,%2,%3}, {%4,%5,%6,%7}, {%8,%9}, {%0,%1,%2,%3};"
                 : "+f"(c[0]), "+f"(c[1]), "+f"(c[2]), "+f"(c[3])
                 : "r"(a[0]), "r"(a[1]), "r"(a[2]), "r"(a[3]), "r"(b[0]), "r"(b[1]));
}
__device__ __forceinline__ u32 mapa_(u32 addr, u32 rank) {
    u32 r; asm("mapa.shared::cluster.u32 %0, %1, %2;" : "=r"(r) : "r"(addr), "r"(rank));
    return r;
}
__device__ __forceinline__ void stclu(u32 addr, u32 v) {
    asm volatile("st.shared::cluster.u32 [%0], %1;" :: "r"(addr), "r"(v) : "memory");
}
__device__ __forceinline__ void cluster_arrive() {
    asm volatile("barrier.cluster.arrive.aligned;" ::: "memory");
}
__device__ __forceinline__ void cluster_wait() {
    asm volatile("barrier.cluster.wait.aligned;" ::: "memory");
}
__device__ __forceinline__ u32 ctarank() {
    u32 r; asm("mov.u32 %0, %%cluster_ctarank;" : "=r"(r)); return r;
}
__device__ __forceinline__ int sw7(int chunk, int row) {
    return (chunk & 24) | ((chunk ^ (row & 7)) & 7);
}
__device__ __forceinline__ float tanh_ap(float x) {
    float y; asm("tanh.approx.f32 %0, %1;" : "=f"(y) : "f"(x)); return y;
}
__device__ __forceinline__ float sigm_ap(float x) {
    return fmaf(tanh_ap(0.5f * x), 0.5f, 0.5f);
}
__device__ __forceinline__ void cpa(u32 dst, const void* src) {
    asm volatile("cp.async.cg.shared.global [%0], [%1], 16;" :: "r"(dst), "l"(src) : "memory");
}
__device__ __forceinline__ void cpcommit() {
    asm volatile("cp.async.commit_group;" ::: "memory");
}
template<int N> __device__ __forceinline__ void cpwait() {
    asm volatile("cp.async.wait_group %0;" :: "n"(N) : "memory");
}

// ---- fp32 -> fp16 convert --------------------------------------------------
__global__ void cvt2h(const float* __restrict__ in, __half2* __restrict__ out, int n2) {
    for (int i = blockIdx.x * blockDim.x + threadIdx.x; i < n2; i += gridDim.x * blockDim.x) {
        float2 v = ((const float2*)in)[i];
        out[i] = __floats2half2_rn(v.x, v.y);
    }
}

// ===========================================================================
// Kernel A: fp16 HMMA GEMM with 3-stage cp.async pipeline (kept from R11).
// xg = x @ W_ih^T + b_ih.  CTA tile 128x64, K-tile 32, 8 warps (4m x 2n).
// ===========================================================================
__global__ __launch_bounds__(256)
void hgemm(const __half* __restrict__ Ah, const __half* __restrict__ Wh,
           const float* __restrict__ bih) {
    __shared__ __align__(16) char hsm[3 * 8192 + 3 * 4096];
    const int tid = threadIdx.x;
    const int lane = tid & 31, warp = tid >> 5;
    const int wm = warp & 3, wn = warp >> 2;
    const size_t mBase = (size_t)blockIdx.y * 128;
    const int nBase = blockIdx.x * 64;

    const int lr = tid >> 2, lc = tid & 3;
    const uint4* aG0 = (const uint4*)(Ah + (mBase + lr) * NIN) + lc;
    const uint4* aG1 = aG0 + (64 * NIN) / 8;
    const uint4* bG  = (const uint4*)(Wh + (size_t)(nBase + lr) * NIN) + lc;
    const int stA = lr * 64 + ((lc ^ ((lr >> 1) & 3)) * 16);

    const u32 aSm = (u32)__cvta_generic_to_shared(hsm);
    const u32 bSm = aSm + 3 * 8192;

    const int rowA = wm * 32 + ((lane >> 3) & 1) * 8 + (lane & 7);
    const int loffA = rowA * 64 + (((lane >> 4) ^ ((rowA >> 1) & 3)) * 16);
    const int rowB = wn * 32 + (lane >> 4) * 8 + (lane & 7);
    const int loffB = rowB * 64 + ((((lane >> 3) & 1) ^ ((rowB >> 1) & 3)) * 16);

    float c[2][4][4];
    #pragma unroll
    for (int mi = 0; mi < 2; mi++)
        #pragma unroll
        for (int ni = 0; ni < 4; ni++)
            #pragma unroll
            for (int q = 0; q < 4; q++) c[mi][ni][q] = 0.f;

    #pragma unroll
    for (int p = 0; p < 2; p++) {
        const u32 da = aSm + p * 8192 + stA;
        cpa(da,        aG0 + p * 4);
        cpa(da + 4096, aG1 + p * 4);
        cpa(bSm + p * 4096 + stA, bG + p * 4);
        cpcommit();
    }

    int slotc = 0, slotl = 2;
    for (int kt = 0; kt < 16; kt++) {
        cpwait<1>();
        __syncthreads();
        if (kt + 2 < 16) {
            const u32 da = aSm + slotl * 8192 + stA;
            cpa(da,        aG0 + (kt + 2) * 4);
            cpa(da + 4096, aG1 + (kt + 2) * 4);
            cpa(bSm + slotl * 4096 + stA, bG + (kt + 2) * 4);
        }
        cpcommit();
        const u32 aB = aSm + slotc * 8192;
        const u32 bB = bSm + slotc * 4096;
        #pragma unroll
        for (int t = 0; t < 2; t++) {
            u32 aF[2][4], bF4[2][4];
            lds4(aF[0][0], aF[0][1], aF[0][2], aF[0][3], aB + (loffA ^ (t << 5)));
            lds4(aF[1][0], aF[1][1], aF[1][2], aF[1][3], aB + ((loffA + 1024) ^ (t << 5)));
            lds4(bF4[0][0], bF4[0][1], bF4[0][2], bF4[0][3], bB + (loffB ^ (t << 5)));
            lds4(bF4[1][0], bF4[1][1], bF4[1][2], bF4[1][3], bB + ((loffB + 1024) ^ (t << 5)));
            #pragma unroll
            for (int mi = 0; mi < 2; mi++) {
                mma16816(c[mi][0], aF[mi], &bF4[0][0]);
                mma16816(c[mi][1], aF[mi], &bF4[0][2]);
                mma16816(c[mi][2], aF[mi], &bF4[1][0]);
                mma16816(c[mi][3], aF[mi], &bF4[1][2]);
            }
        }
        slotc = (slotc + 1 == 3) ? 0 : slotc + 1;
        slotl = (slotl + 1 == 3) ? 0 : slotl + 1;
    }

    const int er = lane >> 2, ec = (lane & 3) * 2;
    #pragma unroll
    for (int mi = 0; mi < 2; mi++) {
        const size_t m0 = mBase + wm * 32 + mi * 16 + er;
        #pragma unroll
        for (int ni = 0; ni < 4; ni++) {
            const int col = nBase + wn * 32 + ni * 8 + ec;
            const float2 bv = *(const float2*)&bih[col];
            float2 o0 = make_float2(c[mi][ni][0] + bv.x, c[mi][ni][1] + bv.y);
            float2 o1 = make_float2(c[mi][ni][2] + bv.x, c[mi][ni][3] + bv.y);
            *(float2*)(g_xg + m0 * G3H + col)       = o0;
            *(float2*)(g_xg + (m0 + 8) * G3H + col) = o1;
        }
    }
}

// ===========================================================================
// Kernel B: tensor-core GRU (R9 structure: split barrier.cluster, W frags in
// registers, split accumulators, xg prefetch between arrive and wait).
// ===========================================================================
__global__ __launch_bounds__(256, 1) __cluster_dims__(CL, 1, 1)
void gru_mma(const float* __restrict__ Whh, const float* __restrict__ bhh) {
    extern __shared__ char sm[];
    char* WS = sm;                 // W staging (dead after prologue)
    char* AS = sm + WBYTES;        // [2 bufs][hi 8KB | lo 8KB]

    const int tid = threadIdx.x;
    const int lane = tid & 31, warp = tid >> 5;
    const u32 q = ctarank();
    const int b0 = (blockIdx.x >> 2) * NBG;

    // ---- prologue: stage + convert + swizzle W slice ----
    for (int t = tid; t < WROWS * 32; t += 256) {
        int row = t >> 5, ch = t & 31;
        int jt = row / 24, rem = row - jt * 24;
        int g = rem >> 3, rr = rem & 7;
        int grow = g * 256 + (int)q * 64 + jt * 8 + rr;
        const float4* src = (const float4*)(Whh + (size_t)grow * H_ + ch * 8);
        float4 f0 = src[0], f1 = src[1];
        __half2 h0 = __floats2half2_rn(f0.x, f0.y), h1 = __floats2half2_rn(f0.z, f0.w);
        __half2 h2 = __floats2half2_rn(f1.x, f1.y), h3 = __floats2half2_rn(f1.z, f1.w);
        uint4 v = make_uint4(*(u32*)&h0, *(u32*)&h1, *(u32*)&h2, *(u32*)&h3);
        *(uint4*)(WS + row * 512 + sw7(ch, row) * 16) = v;
    }
    for (int t = tid; t < (2 * ABUF) / 16; t += 256)
        ((uint4*)AS)[t] = make_uint4(0, 0, 0, 0);
    __syncthreads();

    // ---- hoist W fragments into registers ----
    const u32 wsS = (u32)__cvta_generic_to_shared(WS);
    const int brow = warp * 24 + ((lane >> 4) & 1) * 8 + (lane & 7);
    const int bchl = (lane >> 3) & 1;
    const int nrow = warp * 24 + 16 + (lane & 7);
    u32 bR[16][2], bZ[16][2], bN[16][2];
    #pragma unroll
    for (int kc = 0; kc < 16; kc++) {
        const int cB = kc * 2 + bchl;
        u32 t0, t1, t2, t3;
        lds4(t0, t1, t2, t3, wsS + brow * 512 + sw7(cB, brow) * 16);
        bR[kc][0] = t0; bR[kc][1] = t1; bZ[kc][0] = t2; bZ[kc][1] = t3;
        lds2(bN[kc][0], bN[kc][1], wsS + nrow * 512 + sw7(cB, nrow) * 16);
    }

    // ---- per-thread constants ----
    const int jl = (lane & 3) * 2;
    const int jg = (int)q * 64 + warp * 8 + jl;
    const int m_ = lane >> 2;
    const float2 br = *(const float2*)&bhh[jg];
    const float2 bz = *(const float2*)&bhh[256 + jg];
    const float2 bq = *(const float2*)&bhh[512 + jg];

    const float* xg0 = g_xg + (size_t)(b0 + m_) * T_ * G3H + jg;
    const float* xg1 = g_xg + (size_t)(b0 + m_ + 8) * T_ * G3H + jg;

    const u32 asS = (u32)__cvta_generic_to_shared(AS);
    const int arow = ((lane >> 3) & 1) * 8 + (lane & 7);
    const int achl = (lane >> 4) & 1;

    const int chw = (int)q * 8 + warp;
    const u32 woff0 = m_ * 512 + sw7(chw, m_) * 16 + (lane & 3) * 4;
    const u32 woff1 = woff0 + 8 * 512;

    u32 asR[CL];
    #pragma unroll
    for (int r = 0; r < CL; r++) asR[r] = mapa_(asS, (u32)r);

    float hOld[4] = {0.f, 0.f, 0.f, 0.f};

    float2 xr0 = *(const float2*)xg0;
    float2 xz0 = *(const float2*)(xg0 + 256);
    float2 xn0 = *(const float2*)(xg0 + 512);
    float2 xr1 = *(const float2*)xg1;
    float2 xz1 = *(const float2*)(xg1 + 256);
    float2 xn1 = *(const float2*)(xg1 + 512);

    cluster_arrive(); cluster_wait();   // W + zeroed A visible cluster-wide

    for (int s = 0; s < T_; s++) {
        const u32 abase = asS + (u32)(s & 1) * ABUF;
        float crh[4] = {0,0,0,0}, czh[4] = {0,0,0,0}, cnh[4] = {0,0,0,0};
        float crl[4] = {0,0,0,0}, czl[4] = {0,0,0,0}, cnl[4] = {0,0,0,0};

        #pragma unroll
        for (int kc = 0; kc < 16; kc++) {
            const int cA = kc * 2 + achl;
            const u32 aaddr = abase + arow * 512 + sw7(cA, arow) * 16;
            u32 ah[4], al[4];
            lds4(ah[0], ah[1], ah[2], ah[3], aaddr);
            lds4(al[0], al[1], al[2], al[3], aaddr + 8192);
            mma16816(crh, ah, bR[kc]);
            mma16816(czh, ah, bZ[kc]);
            mma16816(cnh, ah, bN[kc]);
            mma16816(crl, al, bR[kc]);
            mma16816(czl, al, bZ[kc]);
            mma16816(cnl, al, bN[kc]);
        }

        // ---- gates (tanh.approx for both sigmoid and tanh) ----
        float hv[4];
        {
            const float xr[4] = {xr0.x, xr0.y, xr1.x, xr1.y};
            const float xz[4] = {xz0.x, xz0.y, xz1.x, xz1.y};
            const float xn[4] = {xn0.x, xn0.y, xn1.x, xn1.y};
            const float brv[4] = {br.x, br.y, br.x, br.y};
            const float bzv[4] = {bz.x, bz.y, bz.x, bz.y};
            const float bnv[4] = {bq.x, bq.y, bq.x, bq.y};
            #pragma unroll
            for (int i = 0; i < 4; i++) {
                float rr = sigm_ap(xr[i] + crh[i] + crl[i] + brv[i]);
                float zz = sigm_ap(xz[i] + czh[i] + czl[i] + bzv[i]);
                float nn = tanh_ap(xn[i] + rr * (cnh[i] + cnl[i] + bnv[i]));
                hv[i] = (1.f - zz) * nn + zz * hOld[i];
                hOld[i] = hv[i];
            }
        }

        // ---- replicate h (hi/lo fp16) to all CTAs' next A buffer ----
        __half2 hi0 = __floats2half2_rn(hv[0], hv[1]);
        __half2 hi1 = __floats2half2_rn(hv[2], hv[3]);
        float2 f0 = __half22float2(hi0), f1 = __half22float2(hi1);
        __half2 lo0 = __floats2half2_rn(hv[0] - f0.x, hv[1] - f0.y);
        __half2 lo1 = __floats2half2_rn(hv[2] - f1.x, hv[3] - f1.y);
        const u32 nbuf = (u32)((s + 1) & 1) * ABUF;
        #pragma unroll
        for (int r = 0; r < CL; r++) {
            const u32 base = asR[r] + nbuf;
            stclu(base + woff0,        *(u32*)&hi0);
            stclu(base + woff0 + 8192, *(u32*)&lo0);
            stclu(base + woff1,        *(u32*)&hi1);
            stclu(base + woff1 + 8192, *(u32*)&lo1);
        }
        cluster_arrive();

        // hide next-step xg LDG (and final hT store) under the barrier wait
        if (s < T_ - 1) {
            const float* p0 = xg0 + (size_t)(s + 1) * G3H;
            const float* p1 = xg1 + (size_t)(s + 1) * G3H;
            xr0 = *(const float2*)p0;
            xz0 = *(const float2*)(p0 + 256);
            xn0 = *(const float2*)(p0 + 512);
            xr1 = *(const float2*)p1;
            xz1 = *(const float2*)(p1 + 256);
            xn1 = *(const float2*)(p1 + 512);
        } else {
            *(float2*)(g_hT + (size_t)(b0 + m_) * H_ + jg)     = make_float2(hv[0], hv[1]);
            *(float2*)(g_hT + (size_t)(b0 + m_ + 8) * H_ + jg) = make_float2(hv[2], hv[3]);
        }
        cluster_wait();
    }
}

// ===========================================================================
// Kernel C: out[b,c] = hT[b] . fc_w[c] + fc_b[c]
// ===========================================================================
#define NBF 8
__global__ void fc_kernel(const float* __restrict__ fcw,
                          const float* __restrict__ fcb,
                          float* __restrict__ out) {
    __shared__ float hs[NBF][H_];
    const int b0 = blockIdx.x * NBF;
    for (int i = threadIdx.x; i < NBF * H_; i += blockDim.x)
        hs[i >> 8][i & 255] = g_hT[(size_t)b0 * H_ + i];
    __syncthreads();
    const int c = threadIdx.x;
    if (c < NC) {
        float acc[NBF];
        #pragma unroll
        for (int b = 0; b < NBF; b++) acc[b] = fcb[c];
        const float* w = fcw + (size_t)c * H_;
        #pragma unroll 4
        for (int k = 0; k < H_; k++) {
            float wv = w[k];
            #pragma unroll
            for (int b = 0; b < NBF; b++) acc[b] = fmaf(hs[b][k], wv, acc[b]);
        }
        #pragma unroll
        for (int b = 0; b < NBF; b++) out[(size_t)(b0 + b) * NC + c] = acc[b];
    }
}

// ===========================================================================
extern "C" void kernel_launch(void* const* d_in, const int* in_sizes, int n_in,
                              void* d_out, int out_size) {
    const float* x   = (const float*)d_in[0];
    const float* Wih = (const float*)d_in[1];
    const float* Whh = (const float*)d_in[2];
    const float* bih = (const float*)d_in[3];
    const float* bhh = (const float*)d_in[4];
    const float* fcw = (const float*)d_in[5];
    const float* fcb = (const float*)d_in[6];
    float* out = (float*)d_out;

    cudaFuncSetAttribute(gru_mma,
                         cudaFuncAttributeMaxDynamicSharedMemorySize, SMEM_GRU);

    __half2* xh2; cudaGetSymbolAddress((void**)&xh2, g_xh);
    __half2* wh2; cudaGetSymbolAddress((void**)&wh2, g_wh);

    cvt2h<<<2048, 256>>>(x, xh2, (B_ * T_ * NIN) / 2);
    cvt2h<<<256, 256>>>(Wih, wh2, (G3H * NIN) / 2);

    __half* xh; cudaGetSymbolAddress((void**)&xh, g_xh);
    __half* wh; cudaGetSymbolAddress((void**)&wh, g_wh);
    dim3 g1(G3H / 64, (B_ * T_) / 128);
    hgemm<<<g1, 256>>>(xh, wh, bih);

    gru_mma<<<16 * CL, 256, SMEM_GRU>>>(Whh, bhh);
    fc_kernel<<<B_ / NBF, 128>>>(fcw, fcb, out);
}

// round 15
// speedup vs baseline: 2.2057x; 1.2550x over previous
#include <cuda_runtime.h>
#include <cuda_fp16.h>

typedef unsigned long long u64;
typedef unsigned int u32;

#define B_   256
#define T_   512
#define NIN  512
#define H_   256
#define G3H  768
#define NC   101
#define CL   4
#define NBG  16
#define WROWS 192
#define WBYTES (WROWS * 512)
#define ABUF  8192                     // hi plane only
#define SMEM_GRU (WBYTES + 2 * ABUF)   // 114688

// ---- scratch ---------------------------------------------------------------
__device__ float  g_xg[(size_t)B_ * T_ * G3H];
__device__ __half g_xh[(size_t)B_ * T_ * NIN];
__device__ __half g_wh[G3H * NIN];
__device__ float  g_hT[B_ * H_];

// ---- ptx helpers -----------------------------------------------------------
__device__ __forceinline__ void lds4(u32& r0, u32& r1, u32& r2, u32& r3, u32 a) {
    asm volatile("ldmatrix.sync.aligned.m8n8.x4.shared.b16 {%0,%1,%2,%3}, [%4];"
                 : "=r"(r0), "=r"(r1), "=r"(r2), "=r"(r3) : "r"(a));
}
__device__ __forceinline__ void lds2(u32& r0, u32& r1, u32 a) {
    asm volatile("ldmatrix.sync.aligned.m8n8.x2.shared.b16 {%0,%1}, [%2];"
                 : "=r"(r0), "=r"(r1) : "r"(a));
}
__device__ __forceinline__ void mma16816(float* c, const u32* a, const u32* b) {
    asm volatile("mma.sync.aligned.m16n8k16.row.col.f32.f16.f16.f32 "
                 "{%0,%1,%2,%3}, {%4,%5,%6,%7}, {%8,%9}, {%0,%1,%2,%3};"
                 : "+f"(c[0]), "+f"(c[1]), "+f"(c[2]), "+f"(c[3])
                 : "r"(a[0]), "r"(a[1]), "r"(a[2]), "r"(a[3]), "r"(b[0]), "r"(b[1]));
}
__device__ __forceinline__ u32 mapa_(u32 addr, u32 rank) {
    u32 r; asm("mapa.shared::cluster.u32 %0, %1, %2;" : "=r"(r) : "r"(addr), "r"(rank));
    return r;
}
__device__ __forceinline__ void stclu(u32 addr, u32 v) {
    asm volatile("st.shared::cluster.u32 [%0], %1;" :: "r"(addr), "r"(v) : "memory");
}
__device__ __forceinline__ void cluster_arrive() {
    asm volatile("barrier.cluster.arrive.aligned;" ::: "memory");
}
__device__ __forceinline__ void cluster_wait() {
    asm volatile("barrier.cluster.wait.aligned;" ::: "memory");
}
__device__ __forceinline__ u32 ctarank() {
    u32 r; asm("mov.u32 %0, %%cluster_ctarank;" : "=r"(r)); return r;
}
__device__ __forceinline__ int sw7(int chunk, int row) {
    return (chunk & 24) | ((chunk ^ (row & 7)) & 7);
}
__device__ __forceinline__ float tanh_ap(float x) {
    float y; asm("tanh.approx.f32 %0, %1;" : "=f"(y) : "f"(x)); return y;
}
__device__ __forceinline__ float sigm_ap(float x) {
    return fmaf(tanh_ap(0.5f * x), 0.5f, 0.5f);
}
__device__ __forceinline__ void cpa(u32 dst, const void* src) {
    asm volatile("cp.async.cg.shared.global [%0], [%1], 16;" :: "r"(dst), "l"(src) : "memory");
}
__device__ __forceinline__ void cpcommit() {
    asm volatile("cp.async.commit_group;" ::: "memory");
}
template<int N> __device__ __forceinline__ void cpwait() {
    asm volatile("cp.async.wait_group %0;" :: "n"(N) : "memory");
}

// ---- fp32 -> fp16 convert --------------------------------------------------
__global__ void cvt2h(const float* __restrict__ in, __half2* __restrict__ out, int n2) {
    for (int i = blockIdx.x * blockDim.x + threadIdx.x; i < n2; i += gridDim.x * blockDim.x) {
        float2 v = ((const float2*)in)[i];
        out[i] = __floats2half2_rn(v.x, v.y);
    }
}

// ===========================================================================
// Kernel A: fp16 HMMA GEMM with 3-stage cp.async pipeline (unchanged).
// xg = x @ W_ih^T + b_ih.  CTA tile 128x64, K-tile 32, 8 warps (4m x 2n).
// ===========================================================================
__global__ __launch_bounds__(256)
void hgemm(const __half* __restrict__ Ah, const __half* __restrict__ Wh,
           const float* __restrict__ bih) {
    __shared__ __align__(16) char hsm[3 * 8192 + 3 * 4096];
    const int tid = threadIdx.x;
    const int lane = tid & 31, warp = tid >> 5;
    const int wm = warp & 3, wn = warp >> 2;
    const size_t mBase = (size_t)blockIdx.y * 128;
    const int nBase = blockIdx.x * 64;

    const int lr = tid >> 2, lc = tid & 3;
    const uint4* aG0 = (const uint4*)(Ah + (mBase + lr) * NIN) + lc;
    const uint4* aG1 = aG0 + (64 * NIN) / 8;
    const uint4* bG  = (const uint4*)(Wh + (size_t)(nBase + lr) * NIN) + lc;
    const int stA = lr * 64 + ((lc ^ ((lr >> 1) & 3)) * 16);

    const u32 aSm = (u32)__cvta_generic_to_shared(hsm);
    const u32 bSm = aSm + 3 * 8192;

    const int rowA = wm * 32 + ((lane >> 3) & 1) * 8 + (lane & 7);
    const int loffA = rowA * 64 + (((lane >> 4) ^ ((rowA >> 1) & 3)) * 16);
    const int rowB = wn * 32 + (lane >> 4) * 8 + (lane & 7);
    const int loffB = rowB * 64 + ((((lane >> 3) & 1) ^ ((rowB >> 1) & 3)) * 16);

    float c[2][4][4];
    #pragma unroll
    for (int mi = 0; mi < 2; mi++)
        #pragma unroll
        for (int ni = 0; ni < 4; ni++)
            #pragma unroll
            for (int q = 0; q < 4; q++) c[mi][ni][q] = 0.f;

    #pragma unroll
    for (int p = 0; p < 2; p++) {
        const u32 da = aSm + p * 8192 + stA;
        cpa(da,        aG0 + p * 4);
        cpa(da + 4096, aG1 + p * 4);
        cpa(bSm + p * 4096 + stA, bG + p * 4);
        cpcommit();
    }

    int slotc = 0, slotl = 2;
    for (int kt = 0; kt < 16; kt++) {
        cpwait<1>();
        __syncthreads();
        if (kt + 2 < 16) {
            const u32 da = aSm + slotl * 8192 + stA;
            cpa(da,        aG0 + (kt + 2) * 4);
            cpa(da + 4096, aG1 + (kt + 2) * 4);
            cpa(bSm + slotl * 4096 + stA, bG + (kt + 2) * 4);
        }
        cpcommit();
        const u32 aB = aSm + slotc * 8192;
        const u32 bB = bSm + slotc * 4096;
        #pragma unroll
        for (int t = 0; t < 2; t++) {
            u32 aF[2][4], bF4[2][4];
            lds4(aF[0][0], aF[0][1], aF[0][2], aF[0][3], aB + (loffA ^ (t << 5)));
            lds4(aF[1][0], aF[1][1], aF[1][2], aF[1][3], aB + ((loffA + 1024) ^ (t << 5)));
            lds4(bF4[0][0], bF4[0][1], bF4[0][2], bF4[0][3], bB + (loffB ^ (t << 5)));
            lds4(bF4[1][0], bF4[1][1], bF4[1][2], bF4[1][3], bB + ((loffB + 1024) ^ (t << 5)));
            #pragma unroll
            for (int mi = 0; mi < 2; mi++) {
                mma16816(c[mi][0], aF[mi], &bF4[0][0]);
                mma16816(c[mi][1], aF[mi], &bF4[0][2]);
                mma16816(c[mi][2], aF[mi], &bF4[1][0]);
                mma16816(c[mi][3], aF[mi], &bF4[1][2]);
            }
        }
        slotc = (slotc + 1 == 3) ? 0 : slotc + 1;
        slotl = (slotl + 1 == 3) ? 0 : slotl + 1;
    }

    const int er = lane >> 2, ec = (lane & 3) * 2;
    #pragma unroll
    for (int mi = 0; mi < 2; mi++) {
        const size_t m0 = mBase + wm * 32 + mi * 16 + er;
        #pragma unroll
        for (int ni = 0; ni < 4; ni++) {
            const int col = nBase + wn * 32 + ni * 8 + ec;
            const float2 bv = *(const float2*)&bih[col];
            float2 o0 = make_float2(c[mi][ni][0] + bv.x, c[mi][ni][1] + bv.y);
            float2 o1 = make_float2(c[mi][ni][2] + bv.x, c[mi][ni][3] + bv.y);
            *(float2*)(g_xg + m0 * G3H + col)       = o0;
            *(float2*)(g_xg + (m0 + 8) * G3H + col) = o1;
        }
    }
}

// ===========================================================================
// Kernel B: tensor-core GRU, single fp16 h plane (state stays fp32 in regs —
// only the broadcast copy of h is quantized). 48 MMAs/warp/step.
// ===========================================================================
__global__ __launch_bounds__(256, 1) __cluster_dims__(CL, 1, 1)
void gru_mma(const float* __restrict__ Whh, const float* __restrict__ bhh) {
    extern __shared__ char sm[];
    char* WS = sm;                 // W staging (dead after prologue)
    char* AS = sm + WBYTES;        // [2 bufs][8KB hi]

    const int tid = threadIdx.x;
    const int lane = tid & 31, warp = tid >> 5;
    const u32 q = ctarank();
    const int b0 = (blockIdx.x >> 2) * NBG;

    // ---- prologue: stage + convert + swizzle W slice ----
    for (int t = tid; t < WROWS * 32; t += 256) {
        int row = t >> 5, ch = t & 31;
        int jt = row / 24, rem = row - jt * 24;
        int g = rem >> 3, rr = rem & 7;
        int grow = g * 256 + (int)q * 64 + jt * 8 + rr;
        const float4* src = (const float4*)(Whh + (size_t)grow * H_ + ch * 8);
        float4 f0 = src[0], f1 = src[1];
        __half2 h0 = __floats2half2_rn(f0.x, f0.y), h1 = __floats2half2_rn(f0.z, f0.w);
        __half2 h2 = __floats2half2_rn(f1.x, f1.y), h3 = __floats2half2_rn(f1.z, f1.w);
        uint4 v = make_uint4(*(u32*)&h0, *(u32*)&h1, *(u32*)&h2, *(u32*)&h3);
        *(uint4*)(WS + row * 512 + sw7(ch, row) * 16) = v;
    }
    for (int t = tid; t < (2 * ABUF) / 16; t += 256)
        ((uint4*)AS)[t] = make_uint4(0, 0, 0, 0);
    __syncthreads();

    // ---- hoist W fragments into registers ----
    const u32 wsS = (u32)__cvta_generic_to_shared(WS);
    const int brow = warp * 24 + ((lane >> 4) & 1) * 8 + (lane & 7);
    const int bchl = (lane >> 3) & 1;
    const int nrow = warp * 24 + 16 + (lane & 7);
    u32 bR[16][2], bZ[16][2], bN[16][2];
    #pragma unroll
    for (int kc = 0; kc < 16; kc++) {
        const int cB = kc * 2 + bchl;
        u32 t0, t1, t2, t3;
        lds4(t0, t1, t2, t3, wsS + brow * 512 + sw7(cB, brow) * 16);
        bR[kc][0] = t0; bR[kc][1] = t1; bZ[kc][0] = t2; bZ[kc][1] = t3;
        lds2(bN[kc][0], bN[kc][1], wsS + nrow * 512 + sw7(cB, nrow) * 16);
    }

    // ---- per-thread constants ----
    const int jl = (lane & 3) * 2;
    const int jg = (int)q * 64 + warp * 8 + jl;
    const int m_ = lane >> 2;
    const float2 br = *(const float2*)&bhh[jg];
    const float2 bz = *(const float2*)&bhh[256 + jg];
    const float2 bq = *(const float2*)&bhh[512 + jg];

    const float* xg0 = g_xg + (size_t)(b0 + m_) * T_ * G3H + jg;
    const float* xg1 = g_xg + (size_t)(b0 + m_ + 8) * T_ * G3H + jg;

    const u32 asS = (u32)__cvta_generic_to_shared(AS);
    const int arow = ((lane >> 3) & 1) * 8 + (lane & 7);
    const int achl = (lane >> 4) & 1;

    const int chw = (int)q * 8 + warp;
    const u32 woff0 = m_ * 512 + sw7(chw, m_) * 16 + (lane & 3) * 4;
    const u32 woff1 = woff0 + 8 * 512;

    u32 asR[CL];
    #pragma unroll
    for (int r = 0; r < CL; r++) asR[r] = mapa_(asS, (u32)r);

    float hOld[4] = {0.f, 0.f, 0.f, 0.f};

    float2 xr0 = *(const float2*)xg0;
    float2 xz0 = *(const float2*)(xg0 + 256);
    float2 xn0 = *(const float2*)(xg0 + 512);
    float2 xr1 = *(const float2*)xg1;
    float2 xz1 = *(const float2*)(xg1 + 256);
    float2 xn1 = *(const float2*)(xg1 + 512);

    cluster_arrive(); cluster_wait();   // W + zeroed A visible cluster-wide

    for (int s = 0; s < T_; s++) {
        const u32 abase = asS + (u32)(s & 1) * ABUF;
        float cr[4] = {0,0,0,0}, cz[4] = {0,0,0,0}, cn[4] = {0,0,0,0};

        #pragma unroll
        for (int kc = 0; kc < 16; kc++) {
            const int cA = kc * 2 + achl;
            u32 ah[4];
            lds4(ah[0], ah[1], ah[2], ah[3], abase + arow * 512 + sw7(cA, arow) * 16);
            mma16816(cr, ah, bR[kc]);
            mma16816(cz, ah, bZ[kc]);
            mma16816(cn, ah, bN[kc]);
        }

        // ---- gates (state in fp32 registers; only broadcast h is fp16) ----
        float hv[4];
        {
            const float xr[4] = {xr0.x, xr0.y, xr1.x, xr1.y};
            const float xz[4] = {xz0.x, xz0.y, xz1.x, xz1.y};
            const float xn[4] = {xn0.x, xn0.y, xn1.x, xn1.y};
            const float brv[4] = {br.x, br.y, br.x, br.y};
            const float bzv[4] = {bz.x, bz.y, bz.x, bz.y};
            const float bnv[4] = {bq.x, bq.y, bq.x, bq.y};
            #pragma unroll
            for (int i = 0; i < 4; i++) {
                float rr = sigm_ap(xr[i] + cr[i] + brv[i]);
                float zz = sigm_ap(xz[i] + cz[i] + bzv[i]);
                float nn = tanh_ap(xn[i] + rr * (cn[i] + bnv[i]));
                hv[i] = (1.f - zz) * nn + zz * hOld[i];
                hOld[i] = hv[i];
            }
        }

        // ---- replicate h (fp16) to all CTAs' next A buffer ----
        __half2 hi0 = __floats2half2_rn(hv[0], hv[1]);
        __half2 hi1 = __floats2half2_rn(hv[2], hv[3]);
        const u32 nbuf = (u32)((s + 1) & 1) * ABUF;
        #pragma unroll
        for (int r = 0; r < CL; r++) {
            const u32 base = asR[r] + nbuf;
            stclu(base + woff0, *(u32*)&hi0);
            stclu(base + woff1, *(u32*)&hi1);
        }
        cluster_arrive();

        // hide next-step xg LDG (and final hT store) under the barrier wait
        if (s < T_ - 1) {
            const float* p0 = xg0 + (size_t)(s + 1) * G3H;
            const float* p1 = xg1 + (size_t)(s + 1) * G3H;
            xr0 = *(const float2*)p0;
            xz0 = *(const float2*)(p0 + 256);
            xn0 = *(const float2*)(p0 + 512);
            xr1 = *(const float2*)p1;
            xz1 = *(const float2*)(p1 + 256);
            xn1 = *(const float2*)(p1 + 512);
        } else {
            *(float2*)(g_hT + (size_t)(b0 + m_) * H_ + jg)     = make_float2(hv[0], hv[1]);
            *(float2*)(g_hT + (size_t)(b0 + m_ + 8) * H_ + jg) = make_float2(hv[2], hv[3]);
        }
        cluster_wait();
    }
}

// ===========================================================================
// Kernel C: out[b,c] = hT[b] . fc_w[c] + fc_b[c]
// ===========================================================================
#define NBF 8
__global__ void fc_kernel(const float* __restrict__ fcw,
                          const float* __restrict__ fcb,
                          float* __restrict__ out) {
    __shared__ float hs[NBF][H_];
    const int b0 = blockIdx.x * NBF;
    for (int i = threadIdx.x; i < NBF * H_; i += blockDim.x)
        hs[i >> 8][i & 255] = g_hT[(size_t)b0 * H_ + i];
    __syncthreads();
    const int c = threadIdx.x;
    if (c < NC) {
        float acc[NBF];
        #pragma unroll
        for (int b = 0; b < NBF; b++) acc[b] = fcb[c];
        const float* w = fcw + (size_t)c * H_;
        #pragma unroll 4
        for (int k = 0; k < H_; k++) {
            float wv = w[k];
            #pragma unroll
            for (int b = 0; b < NBF; b++) acc[b] = fmaf(hs[b][k], wv, acc[b]);
        }
        #pragma unroll
        for (int b = 0; b < NBF; b++) out[(size_t)(b0 + b) * NC + c] = acc[b];
    }
}

// ===========================================================================
extern "C" void kernel_launch(void* const* d_in, const int* in_sizes, int n_in,
                              void* d_out, int out_size) {
    const float* x   = (const float*)d_in[0];
    const float* Wih = (const float*)d_in[1];
    const float* Whh = (const float*)d_in[2];
    const float* bih = (const float*)d_in[3];
    const float* bhh = (const float*)d_in[4];
    const float* fcw = (const float*)d_in[5];
    const float* fcb = (const float*)d_in[6];
    float* out = (float*)d_out;

    cudaFuncSetAttribute(gru_mma,
                         cudaFuncAttributeMaxDynamicSharedMemorySize, SMEM_GRU);

    __half2* xh2; cudaGetSymbolAddress((void**)&xh2, g_xh);
    __half2* wh2; cudaGetSymbolAddress((void**)&wh2, g_wh);

    cvt2h<<<2048, 256>>>(x, xh2, (B_ * T_ * NIN) / 2);
    cvt2h<<<256, 256>>>(Wih, wh2, (G3H * NIN) / 2);

    __half* xh; cudaGetSymbolAddress((void**)&xh, g_xh);
    __half* wh; cudaGetSymbolAddress((void**)&wh, g_wh);
    dim3 g1(G3H / 64, (B_ * T_) / 128);
    hgemm<<<g1, 256>>>(xh, wh, bih);

    gru_mma<<<16 * CL, 256, SMEM_GRU>>>(Whh, bhh);
    fc_kernel<<<B_ / NBF, 128>>>(fcw, fcb, out);
}